// round 5
// baseline (speedup 1.0000x reference)
#include <cuda_runtime.h>
#include <cuda_bf16.h>

// DiagonalSSM closed form: y[b,t] = Σ_{k<4} c[k]·x[b,t-k], c[k] = α·Σ_n A[n]^k.
// Latency-floor regime: 32 blocks (1 per batch row), branch-free halo,
// register-only x path, single barrier.

#define B_DIM    32
#define T_DIM    2048
#define N_DIM    2048
#define NTHREADS 256

__global__ __launch_bounds__(NTHREADS)
void ssm_conv_kernel(const float* __restrict__ x,
                     const float* __restrict__ A,
                     const float* __restrict__ alpha_p,
                     float* __restrict__ y)
{
    __shared__ float s_warp[8][4];   // [warp][p1,p2,p3,pad] — row-contiguous

    const int tid  = threadIdx.x;
    const int lane = tid & 31;
    const int warp = tid >> 5;

    const int b     = blockIdx.x;          // one block per batch row
    const int tbase = tid << 3;            // 8 outputs per thread
    const float* __restrict__ xb = x + b * T_DIM;

    // ---- Branch-free loads, all issued up front ----
    const int hoff = (tid == 0) ? 0 : (tbase - 4);   // clamp (predicated, no BSSY)
    const float hmask = (tid == 0) ? 0.0f : 1.0f;
    float4 xh  = *(const float4*)(xb + hoff);        // x[t-4..t-1] (masked for t0)
    float4 xq0 = *(const float4*)(xb + tbase);       // x[t  ..t+3]
    float4 xq1 = *(const float4*)(xb + tbase + 4);   // x[t+4..t+7]
    float4 a0  = ((const float4*)A)[tid];
    float4 a1  = ((const float4*)A)[tid + NTHREADS];
    const float alpha = *alpha_p;

    xh.x *= hmask; xh.y *= hmask; xh.z *= hmask; xh.w *= hmask;

    // ---- c[k] partials: k=1..3, chain depth 2 ----
    float av[8] = { a0.x, a0.y, a0.z, a0.w, a1.x, a1.y, a1.z, a1.w };
    float p1 = 0.f, p2 = 0.f, p3 = 0.f;
    #pragma unroll
    for (int i = 0; i < 8; ++i) {
        float a  = av[i];
        float a2 = a * a;
        p1 += a; p2 += a2; p3 += a2 * a;
    }
    #pragma unroll
    for (int off = 16; off; off >>= 1) {
        p1 += __shfl_xor_sync(0xffffffffu, p1, off);
        p2 += __shfl_xor_sync(0xffffffffu, p2, off);
        p3 += __shfl_xor_sync(0xffffffffu, p3, off);
    }
    if (lane == 0) {
        s_warp[warp][0] = p1; s_warp[warp][1] = p2; s_warp[warp][2] = p3;
    }
    __syncthreads();

    // Broadcast finish (every thread sums the 8 warp partials; no 2nd barrier)
    float s1 = 0.f, s2 = 0.f, s3 = 0.f;
    #pragma unroll
    for (int w = 0; w < 8; ++w) {
        s1 += s_warp[w][0]; s2 += s_warp[w][1]; s3 += s_warp[w][2];
    }
    const float c0 = alpha * (float)N_DIM;
    const float c1 = alpha * s1;
    const float c2 = alpha * s2;
    const float c3 = alpha * s3;

    // ---- 4-tap conv, 8 outputs, registers only ----
    float4 o0, o1;
    o0.x = fmaf(c0, xq0.x, fmaf(c1, xh.w,  fmaf(c2, xh.z,  c3 * xh.y )));
    o0.y = fmaf(c0, xq0.y, fmaf(c1, xq0.x, fmaf(c2, xh.w,  c3 * xh.z )));
    o0.z = fmaf(c0, xq0.z, fmaf(c1, xq0.y, fmaf(c2, xq0.x, c3 * xh.w )));
    o0.w = fmaf(c0, xq0.w, fmaf(c1, xq0.z, fmaf(c2, xq0.y, c3 * xq0.x)));
    o1.x = fmaf(c0, xq1.x, fmaf(c1, xq0.w, fmaf(c2, xq0.z, c3 * xq0.y)));
    o1.y = fmaf(c0, xq1.y, fmaf(c1, xq1.x, fmaf(c2, xq0.w, c3 * xq0.z)));
    o1.z = fmaf(c0, xq1.z, fmaf(c1, xq1.y, fmaf(c2, xq1.x, c3 * xq0.w)));
    o1.w = fmaf(c0, xq1.w, fmaf(c1, xq1.z, fmaf(c2, xq1.y, c3 * xq1.x)));

    float* yb = y + b * T_DIM + tbase;
    *(float4*)(yb)     = o0;
    *(float4*)(yb + 4) = o1;
}

extern "C" void kernel_launch(void* const* d_in, const int* in_sizes, int n_in,
                              void* d_out, int out_size)
{
    const float* x     = (const float*)d_in[0];  // [32, 2048]
    const float* A     = (const float*)d_in[1];  // [2048]
    const float* alpha = (const float*)d_in[2];  // scalar
    float*       y     = (float*)d_out;          // [32, 2048]

    (void)in_sizes; (void)n_in; (void)out_size;

    ssm_conv_kernel<<<B_DIM, NTHREADS>>>(x, A, alpha, y);  // 32 blocks
}